// round 3
// baseline (speedup 1.0000x reference)
#include <cuda_runtime.h>
#include <math.h>

#define NN 100000
#define NE 1600000
#define ETOT (NE + NN)
#define H3 3
#define D64 64
#define HD192 192
#define D21 21
#define HD63 63
#define NG 8
#define NCLS 10
#define EPSBN 1e-5f

// ---------------- scratch (device globals; no allocs allowed) ----------------
__device__ float g_xl[(size_t)NN * HD192];
__device__ float g_xr[(size_t)NN * HD192];
__device__ float g_agg[(size_t)NN * HD192];
__device__ float g_h[(size_t)NN * HD192];
__device__ float g_h2[(size_t)NN * D64];
__device__ float g_logit[(size_t)ETOT * H3];
__device__ float g_m[NN * H3];
__device__ float g_z[NN * H3];
__device__ float g_bnsum[HD192];
__device__ float g_bnsq[HD192];
__device__ float g_pool[NG * D64];
__device__ float g_cnt[NG];

// ---------------- helpers ----------------
__device__ __forceinline__ void atomicMaxF(float* addr, float v) {
    // bit-ordering trick: signed max for >=0, unsigned min for <0.
    if (v >= 0.f) atomicMax((int*)addr, __float_as_int(v));
    else          atomicMin((unsigned int*)addr, __float_as_uint(v));
}

// ---------------- resets ----------------
__global__ void reset_small_kernel() {
    int t = threadIdx.x;
    if (t < HD192) { g_bnsum[t] = 0.f; g_bnsq[t] = 0.f; }
    if (t < NG * D64) g_pool[t] = 0.f;
    if (t < NG) g_cnt[t] = 0.f;
}

__global__ void reset_layer_kernel(int hd) {
    size_t n = (size_t)NN * hd;
    size_t stride = (size_t)gridDim.x * blockDim.x;
    for (size_t i = (size_t)blockIdx.x * blockDim.x + threadIdx.x; i < n; i += stride) {
        g_agg[i] = 0.f;
        if (i < (size_t)NN * H3) { g_m[i] = -INFINITY; g_z[i] = 0.f; }
    }
}

// ---------------- GEMM: C[M,N] = A[M,K] @ B[K,N], optional relu on A ----------------
#define BM 64
#define BN 64
#define BKK 16
__global__ void gemm_kernel(const float* __restrict__ A, const float* __restrict__ B,
                            float* __restrict__ C, int M, int N, int K, int reluA) {
    __shared__ float sA[BKK][BM + 1];
    __shared__ float sB[BKK][BN + 1];
    int tx = threadIdx.x & 15, ty = threadIdx.x >> 4;
    int row0 = blockIdx.y * BM, col0 = blockIdx.x * BN;
    float acc[4][4] = {};
    for (int k0 = 0; k0 < K; k0 += BKK) {
        #pragma unroll
        for (int i = threadIdx.x; i < BM * BKK; i += 256) {
            int r = i / BKK, c = i % BKK;
            int gr = row0 + r;
            float v = (gr < M) ? A[(size_t)gr * K + (k0 + c)] : 0.f;
            if (reluA) v = fmaxf(v, 0.f);
            sA[c][r] = v;
        }
        #pragma unroll
        for (int i = threadIdx.x; i < BKK * BN; i += 256) {
            int r = i / BN, c = i % BN;
            int gc = col0 + c;
            sB[r][c] = (gc < N) ? B[(size_t)(k0 + r) * N + gc] : 0.f;
        }
        __syncthreads();
        #pragma unroll
        for (int kk = 0; kk < BKK; kk++) {
            float a[4], b[4];
            #pragma unroll
            for (int i = 0; i < 4; i++) a[i] = sA[kk][ty * 4 + i];
            #pragma unroll
            for (int j = 0; j < 4; j++) b[j] = sB[kk][tx * 4 + j];
            #pragma unroll
            for (int i = 0; i < 4; i++)
                #pragma unroll
                for (int j = 0; j < 4; j++) acc[i][j] += a[i] * b[j];
        }
        __syncthreads();
    }
    #pragma unroll
    for (int i = 0; i < 4; i++) {
        int r = row0 + ty * 4 + i;
        if (r >= M) continue;
        #pragma unroll
        for (int j = 0; j < 4; j++) {
            int c = col0 + tx * 4 + j;
            if (c < N) C[(size_t)r * N + c] = acc[i][j];
        }
    }
}

// ---------------- edge kernels (warp per edge) ----------------
template <int D>
__global__ void edge_logits_k(const int* __restrict__ src, const int* __restrict__ dst,
                              const float* __restrict__ att) {
    const int HD = 3 * D;
    int w = (blockIdx.x * blockDim.x + threadIdx.x) >> 5;
    int lane = threadIdx.x & 31;
    if (w >= ETOT) return;
    int s, d;
    if (w < NE) { s = src[w]; d = dst[w]; } else { s = d = w - NE; }
    const float* pl = g_xl + (size_t)s * HD;
    const float* pr = g_xr + (size_t)d * HD;
    #pragma unroll
    for (int h = 0; h < 3; h++) {
        float acc = 0.f;
        for (int cc = lane; cc < D; cc += 32) {
            int c = h * D + cc;
            float v = pl[c] + pr[c];
            v = (v > 0.f) ? v : 0.2f * v;
            acc += __ldg(&att[c]) * v;
        }
        #pragma unroll
        for (int o = 16; o > 0; o >>= 1) acc += __shfl_xor_sync(0xffffffffu, acc, o);
        if (lane == 0) {
            g_logit[(size_t)w * 3 + h] = acc;
            atomicMaxF(&g_m[d * 3 + h], acc);
        }
    }
}

__global__ void edge_softmax_k(const int* __restrict__ dst) {
    int e = blockIdx.x * blockDim.x + threadIdx.x;
    if (e >= ETOT) return;
    int d = (e < NE) ? dst[e] : e - NE;
    #pragma unroll
    for (int h = 0; h < 3; h++) {
        float ez = expf(g_logit[(size_t)e * 3 + h] - g_m[d * 3 + h]);
        g_logit[(size_t)e * 3 + h] = ez;
        atomicAdd(&g_z[d * 3 + h], ez);
    }
}

template <int D>
__global__ void edge_agg_k(const int* __restrict__ src, const int* __restrict__ dst) {
    const int HD = 3 * D;
    int w = (blockIdx.x * blockDim.x + threadIdx.x) >> 5;
    int lane = threadIdx.x & 31;
    if (w >= ETOT) return;
    int s, d;
    if (w < NE) { s = src[w]; d = dst[w]; } else { s = d = w - NE; }
    const float* pl = g_xl + (size_t)s * HD;
    float* pa = g_agg + (size_t)d * HD;
    #pragma unroll
    for (int h = 0; h < 3; h++) {
        float ez = g_logit[(size_t)w * 3 + h];
        for (int cc = lane; cc < D; cc += 32)
            atomicAdd(&pa[h * D + cc], pl[h * D + cc] * ez);
    }
}

// ---------------- finalize kernels ----------------
// layer 1: normalize, +bias, relu, write h, accumulate BN stats
__global__ void finalize1_kernel(const float* __restrict__ b1) {
    int c = threadIdx.x;               // 0..191
    int per = (NN + gridDim.x - 1) / gridDim.x;
    int r0 = blockIdx.x * per;
    int r1 = min(NN, r0 + per);
    int h = c >> 6;
    float s = 0.f, sq = 0.f;
    for (int n = r0; n < r1; n++) {
        float v = g_agg[(size_t)n * HD192 + c] / g_z[n * H3 + h] + b1[c];
        v = fmaxf(v, 0.f);
        g_h[(size_t)n * HD192 + c] = v;
        s += v; sq += v * v;
    }
    atomicAdd(&g_bnsum[c], s);
    atomicAdd(&g_bnsq[c], sq);
}

__global__ void bn_apply_kernel(const float* __restrict__ gamma, const float* __restrict__ beta) {
    size_t idx = (size_t)blockIdx.x * blockDim.x + threadIdx.x;
    if (idx >= (size_t)NN * HD192) return;
    int c = (int)(idx % HD192);
    float mu = g_bnsum[c] * (1.f / NN);
    float var = g_bnsq[c] * (1.f / NN) - mu * mu;
    g_h[idx] = (g_h[idx] - mu) * rsqrtf(var + EPSBN) * gamma[c] + beta[c];
}

// layer 2: head-mean, +bias, write h2, fused pooling
__global__ void finalize2_kernel(const float* __restrict__ b2, const int* __restrict__ batch) {
    int idx = blockIdx.x * blockDim.x + threadIdx.x;
    if (idx >= NN * D64) return;
    int n = idx >> 6, d = idx & 63;
    float v = 0.f;
    #pragma unroll
    for (int h = 0; h < 3; h++)
        v += g_agg[(size_t)n * HD192 + h * D64 + d] / g_z[n * H3 + h];
    v = v * (1.f / 3.f) + b2[d];
    g_h2[idx] = v;
    int b = batch[n];
    atomicAdd(&g_pool[b * D64 + d], v);
    if (d == 0) atomicAdd(&g_cnt[b], 1.f);
}

__global__ void classifier_kernel(const float* __restrict__ Wc, const float* __restrict__ bc,
                                  float* __restrict__ out) {
    int t = threadIdx.x;
    if (t >= NG * NCLS) return;
    int g = t / NCLS, j = t % NCLS;
    float cnt = fmaxf(g_cnt[g], 1.f);
    float s = bc[j];
    #pragma unroll
    for (int d = 0; d < D64; d++)
        s += (g_pool[g * D64 + d] / cnt) * Wc[d * NCLS + j];
    out[t] = s;
}

// layer 3: head-mean, +bias, write color to out[80:]
__global__ void finalize3_kernel(const float* __restrict__ b3, float* __restrict__ out) {
    int idx = blockIdx.x * blockDim.x + threadIdx.x;
    if (idx >= NN * D21) return;
    int n = idx / D21, c = idx % D21;
    float v = 0.f;
    #pragma unroll
    for (int h = 0; h < 3; h++)
        v += g_agg[(size_t)n * HD63 + h * D21 + c] / g_z[n * H3 + h];
    out[NG * NCLS + idx] = v * (1.f / 3.f) + b3[c];
}

// ---------------- launch ----------------
extern "C" void kernel_launch(void* const* d_in, const int* in_sizes, int n_in,
                              void* d_out, int out_size) {
    const float* x     = (const float*)d_in[0];
    const int*   ei    = (const int*)d_in[1];
    const int*   batch = (const int*)d_in[2];
    const float* Wl1   = (const float*)d_in[3];
    const float* Wr1   = (const float*)d_in[4];
    const float* att1  = (const float*)d_in[5];
    const float* b1    = (const float*)d_in[6];
    const float* gamma = (const float*)d_in[7];
    const float* beta  = (const float*)d_in[8];
    const float* Wl2   = (const float*)d_in[9];
    const float* Wr2   = (const float*)d_in[10];
    const float* att2  = (const float*)d_in[11];
    const float* b2    = (const float*)d_in[12];
    const float* Wl3   = (const float*)d_in[13];
    const float* Wr3   = (const float*)d_in[14];
    const float* att3  = (const float*)d_in[15];
    const float* b3    = (const float*)d_in[16];
    const float* Wc    = (const float*)d_in[17];
    const float* bc    = (const float*)d_in[18];
    float* out = (float*)d_out;

    const int* src  = ei;
    const int* dstp = ei + NE;

    float *pxl, *pxr, *ph, *ph2;
    cudaGetSymbolAddress((void**)&pxl, g_xl);
    cudaGetSymbolAddress((void**)&pxr, g_xr);
    cudaGetSymbolAddress((void**)&ph,  g_h);
    cudaGetSymbolAddress((void**)&ph2, g_h2);

    const int eb_warp = (int)(((long long)ETOT * 32 + 255) / 256);
    const int eb_thr  = (ETOT + 255) / 256;

    reset_small_kernel<<<1, 512>>>();

    // ---- layer 1: 128 -> 3x64 concat ----
    dim3 g1((HD192 + BN - 1) / BN, (NN + BM - 1) / BM);
    gemm_kernel<<<g1, 256>>>(x, Wl1, pxl, NN, HD192, 128, 0);
    gemm_kernel<<<g1, 256>>>(x, Wr1, pxr, NN, HD192, 128, 0);
    reset_layer_kernel<<<4096, 256>>>(HD192);
    edge_logits_k<D64><<<eb_warp, 256>>>(src, dstp, att1);
    edge_softmax_k<<<eb_thr, 256>>>(dstp);
    edge_agg_k<D64><<<eb_warp, 256>>>(src, dstp);
    finalize1_kernel<<<256, HD192>>>(b1);
    bn_apply_kernel<<<(NN * HD192 + 255) / 256, 256>>>(gamma, beta);

    // ---- layer 2: 192 -> 3x64 mean ----
    gemm_kernel<<<g1, 256>>>(ph, Wl2, pxl, NN, HD192, HD192, 0);
    gemm_kernel<<<g1, 256>>>(ph, Wr2, pxr, NN, HD192, HD192, 0);
    reset_layer_kernel<<<4096, 256>>>(HD192);
    edge_logits_k<D64><<<eb_warp, 256>>>(src, dstp, att2);
    edge_softmax_k<<<eb_thr, 256>>>(dstp);
    edge_agg_k<D64><<<eb_warp, 256>>>(src, dstp);
    finalize2_kernel<<<(NN * D64 + 255) / 256, 256>>>(b2, batch);
    classifier_kernel<<<1, 128>>>(Wc, bc, out);

    // ---- layer 3: relu(h2): 64 -> 3x21 mean ----
    dim3 g3((HD63 + BN - 1) / BN, (NN + BM - 1) / BM);
    gemm_kernel<<<g3, 256>>>(ph2, Wl3, pxl, NN, HD63, D64, 1);
    gemm_kernel<<<g3, 256>>>(ph2, Wr3, pxr, NN, HD63, D64, 1);
    reset_layer_kernel<<<4096, 256>>>(HD63);
    edge_logits_k<D21><<<eb_warp, 256>>>(src, dstp, att3);
    edge_softmax_k<<<eb_thr, 256>>>(dstp);
    edge_agg_k<D21><<<eb_warp, 256>>>(src, dstp);
    finalize3_kernel<<<(NN * D21 + 255) / 256, 256>>>(b3, out);
}

// round 5
// speedup vs baseline: 2.6598x; 2.6598x over previous
#include <cuda_runtime.h>
#include <math.h>

#define NN 100000
#define NE 1600000
#define ETOT (NE + NN)
#define HD192 192
#define D64 64
#define HD63 63
#define D21 21
#define NG 8
#define NCLS 10
#define EPSBN 1e-5f

// ---------------- scratch (device globals; no allocs allowed) ----------------
__device__ float g_xl[(size_t)NN * HD192];
__device__ float g_xr[(size_t)NN * HD192];
__device__ float g_h[(size_t)NN * HD192];
__device__ float g_h2[(size_t)NN * D64];
__device__ int   g_counts[NN];
__device__ int   g_rowptr[NN + 1];
__device__ int   g_cursor[NN];
__device__ int   g_col[ETOT];
__device__ float g_bnsum[HD192];
__device__ float g_bnsq[HD192];
__device__ float g_bnscale[HD192];
__device__ float g_bnshift[HD192];
__device__ float g_pool[NG * D64];
__device__ float g_cnt[NG];

// ---------------- small resets ----------------
__global__ void reset_small_kernel() {
    int t = threadIdx.x;
    if (t < HD192) { g_bnsum[t] = 0.f; g_bnsq[t] = 0.f; }
    if (t < NG * D64) g_pool[t] = 0.f;
    if (t < NG) g_cnt[t] = 0.f;
}

// ---------------- CSR build (dst-sorted, rebuilt each launch) ----------------
__global__ void init_counts_kernel() {
    int i = blockIdx.x * blockDim.x + threadIdx.x;
    if (i < NN) g_counts[i] = 1;   // self loop
}

__global__ void hist_kernel(const int* __restrict__ dst) {
    int e = blockIdx.x * blockDim.x + threadIdx.x;
    if (e < NE) atomicAdd(&g_counts[dst[e]], 1);
}

__global__ void scan_kernel() {
    __shared__ int ss[1024];
    int t = threadIdx.x;
    const int CH = (NN + 1023) / 1024;
    int lo = t * CH, hi = min(NN, lo + CH);
    int s = 0;
    for (int i = lo; i < hi; i++) s += g_counts[i];
    ss[t] = s;
    __syncthreads();
    for (int off = 1; off < 1024; off <<= 1) {
        int v = (t >= off) ? ss[t - off] : 0;
        __syncthreads();
        ss[t] += v;
        __syncthreads();
    }
    int pre = (t == 0) ? 0 : ss[t - 1];
    for (int i = lo; i < hi; i++) {
        g_rowptr[i] = pre; g_cursor[i] = pre; pre += g_counts[i];
    }
    if (t == 1023) g_rowptr[NN] = ss[1023];
}

__global__ void csr_fill_kernel(const int* __restrict__ src, const int* __restrict__ dst) {
    int e = blockIdx.x * blockDim.x + threadIdx.x;
    if (e >= ETOT) return;
    int s, d;
    if (e < NE) { s = src[e]; d = dst[e]; } else { s = d = e - NE; }
    int pos = atomicAdd(&g_cursor[d], 1);
    g_col[pos] = s;
}

// ---------------- GEMM: C[M,N] = f(A)[M,K] @ B[K,N] ----------------
// mode: 0 = identity, 1 = relu(A), 2 = BN(A) via g_bnscale/g_bnshift
#define BM 128
#define BN 64
#define BK 16
__global__ void gemm_kernel(const float* __restrict__ A, const float* __restrict__ B,
                            float* __restrict__ C, int M, int N, int K, int mode) {
    __shared__ float sA[BK][BM + 4];
    __shared__ float sB[BK][BN + 4];
    int tid = threadIdx.x;
    int tx = tid & 15, ty = tid >> 4;
    int row0 = blockIdx.y * BM, col0 = blockIdx.x * BN;
    float acc[8][4] = {};
    for (int k0 = 0; k0 < K; k0 += BK) {
        #pragma unroll
        for (int l = 0; l < 2; l++) {
            int i = tid + l * 256;            // float4 slot, 512 total
            int r = i >> 2, c4 = (i & 3) * 4;
            int gr = row0 + r;
            float4 v = make_float4(0.f, 0.f, 0.f, 0.f);
            if (gr < M) v = *(const float4*)&A[(size_t)gr * K + k0 + c4];
            float vv[4] = {v.x, v.y, v.z, v.w};
            #pragma unroll
            for (int q = 0; q < 4; q++) {
                float f = vv[q];
                int kc = k0 + c4 + q;
                if (mode == 1) f = fmaxf(f, 0.f);
                else if (mode == 2) f = f * g_bnscale[kc] + g_bnshift[kc];
                sA[c4 + q][r] = f;
            }
        }
        #pragma unroll
        for (int l = 0; l < 4; l++) {
            int i = tid + l * 256;
            int r = i >> 6, c = i & 63;
            int gc = col0 + c;
            sB[r][c] = (gc < N) ? B[(size_t)(k0 + r) * N + gc] : 0.f;
        }
        __syncthreads();
        #pragma unroll
        for (int kk = 0; kk < BK; kk++) {
            float4 b4 = *(const float4*)&sB[kk][tx * 4];
            float4 a0 = *(const float4*)&sA[kk][ty * 8];
            float4 a1 = *(const float4*)&sA[kk][ty * 8 + 4];
            float a[8] = {a0.x, a0.y, a0.z, a0.w, a1.x, a1.y, a1.z, a1.w};
            float b[4] = {b4.x, b4.y, b4.z, b4.w};
            #pragma unroll
            for (int i = 0; i < 8; i++)
                #pragma unroll
                for (int j = 0; j < 4; j++) acc[i][j] += a[i] * b[j];
        }
        __syncthreads();
    }
    #pragma unroll
    for (int i = 0; i < 8; i++) {
        int r = row0 + ty * 8 + i;
        if (r >= M) continue;
        #pragma unroll
        for (int j = 0; j < 4; j++) {
            int c = col0 + tx * 4 + j;
            if (c < N) C[(size_t)r * N + c] = acc[i][j];
        }
    }
}

// ---------------- fused GAT layers (warp per node, online softmax) ----------------
// HD=192, head = i/2 for element c = lane + 32*i (i=0..5)

#define ONLINE_UPDATE(P, M, Z, A0, A1, X0, X1)                          \
    if (P > M) {                                                         \
        float sc_ = __expf(M - P); Z = Z * sc_ + 1.f;                    \
        A0 = A0 * sc_ + X0; A1 = A1 * sc_ + X1; M = P;                   \
    } else {                                                             \
        float w_ = __expf(P - M); Z += w_;                               \
        A0 += X0 * w_; A1 += X1 * w_;                                    \
    }

__global__ void gat1_kernel(const float* __restrict__ att, const float* __restrict__ b1) {
    __shared__ float sbn[HD192], sbq[HD192];
    int tid = threadIdx.x;
    if (tid < HD192) { sbn[tid] = 0.f; sbq[tid] = 0.f; }
    __syncthreads();
    int lane = tid & 31, wib = tid >> 5;
    int n = blockIdx.x * 8 + wib;
    if (n < NN) {
        float attr[6], xrr[6], acc[6], xv[6];
        const float* pr = g_xr + (size_t)n * HD192;
        #pragma unroll
        for (int i = 0; i < 6; i++) {
            int c = lane + 32 * i;
            attr[i] = att[c]; xrr[i] = pr[c]; acc[i] = 0.f;
        }
        float m0 = -INFINITY, m1 = -INFINITY, m2 = -INFINITY;
        float z0 = 0.f, z1 = 0.f, z2 = 0.f;
        int e1 = g_rowptr[n + 1];
        for (int e = g_rowptr[n]; e < e1; e++) {
            int s = g_col[e];
            const float* px = g_xl + (size_t)s * HD192;
            float p0 = 0.f, p1 = 0.f, p2 = 0.f;
            #pragma unroll
            for (int i = 0; i < 6; i++) {
                int c = lane + 32 * i;
                float xvv = px[c]; xv[i] = xvv;
                float v = xvv + xrr[i];
                v = (v > 0.f) ? v : 0.2f * v;
                float pv = attr[i] * v;
                if (i < 2) p0 += pv; else if (i < 4) p1 += pv; else p2 += pv;
            }
            #pragma unroll
            for (int o = 16; o > 0; o >>= 1) {
                p0 += __shfl_xor_sync(0xffffffffu, p0, o);
                p1 += __shfl_xor_sync(0xffffffffu, p1, o);
                p2 += __shfl_xor_sync(0xffffffffu, p2, o);
            }
            ONLINE_UPDATE(p0, m0, z0, acc[0], acc[1], xv[0], xv[1])
            ONLINE_UPDATE(p1, m1, z1, acc[2], acc[3], xv[2], xv[3])
            ONLINE_UPDATE(p2, m2, z2, acc[4], acc[5], xv[4], xv[5])
        }
        float iz[3] = {1.f / z0, 1.f / z1, 1.f / z2};
        float* ph = g_h + (size_t)n * HD192;
        #pragma unroll
        for (int i = 0; i < 6; i++) {
            int c = lane + 32 * i;
            float o = acc[i] * iz[i >> 1] + b1[c];
            o = fmaxf(o, 0.f);
            ph[c] = o;
            atomicAdd(&sbn[c], o);
            atomicAdd(&sbq[c], o * o);
        }
    }
    __syncthreads();
    if (tid < HD192) {
        atomicAdd(&g_bnsum[tid], sbn[tid]);
        atomicAdd(&g_bnsq[tid], sbq[tid]);
    }
}

__global__ void bn_prep_kernel(const float* __restrict__ gamma, const float* __restrict__ beta) {
    int c = threadIdx.x;
    if (c < HD192) {
        float mu = g_bnsum[c] * (1.f / NN);
        float var = g_bnsq[c] * (1.f / NN) - mu * mu;
        float s = gamma[c] * rsqrtf(var + EPSBN);
        g_bnscale[c] = s;
        g_bnshift[c] = beta[c] - mu * s;
    }
}

__global__ void gat2_kernel(const float* __restrict__ att, const float* __restrict__ b2,
                            const int* __restrict__ batch) {
    int tid = threadIdx.x;
    int lane = tid & 31, wib = tid >> 5;
    int n = blockIdx.x * 8 + wib;
    if (n >= NN) return;
    float attr[6], xrr[6], acc[6], xv[6];
    const float* pr = g_xr + (size_t)n * HD192;
    #pragma unroll
    for (int i = 0; i < 6; i++) {
        int c = lane + 32 * i;
        attr[i] = att[c]; xrr[i] = pr[c]; acc[i] = 0.f;
    }
    float m0 = -INFINITY, m1 = -INFINITY, m2 = -INFINITY;
    float z0 = 0.f, z1 = 0.f, z2 = 0.f;
    int e1 = g_rowptr[n + 1];
    for (int e = g_rowptr[n]; e < e1; e++) {
        int s = g_col[e];
        const float* px = g_xl + (size_t)s * HD192;
        float p0 = 0.f, p1 = 0.f, p2 = 0.f;
        #pragma unroll
        for (int i = 0; i < 6; i++) {
            int c = lane + 32 * i;
            float xvv = px[c]; xv[i] = xvv;
            float v = xvv + xrr[i];
            v = (v > 0.f) ? v : 0.2f * v;
            float pv = attr[i] * v;
            if (i < 2) p0 += pv; else if (i < 4) p1 += pv; else p2 += pv;
        }
        #pragma unroll
        for (int o = 16; o > 0; o >>= 1) {
            p0 += __shfl_xor_sync(0xffffffffu, p0, o);
            p1 += __shfl_xor_sync(0xffffffffu, p1, o);
            p2 += __shfl_xor_sync(0xffffffffu, p2, o);
        }
        ONLINE_UPDATE(p0, m0, z0, acc[0], acc[1], xv[0], xv[1])
        ONLINE_UPDATE(p1, m1, z1, acc[2], acc[3], xv[2], xv[3])
        ONLINE_UPDATE(p2, m2, z2, acc[4], acc[5], xv[4], xv[5])
    }
    float iz0 = 1.f / z0, iz1 = 1.f / z1, iz2 = 1.f / z2;
    // element c = lane + 32i maps to out dim d = c % 64, head = i/2;
    // acc[0],acc[2],acc[4] -> d=lane ; acc[1],acc[3],acc[5] -> d=lane+32
    float v0 = (acc[0] * iz0 + acc[2] * iz1 + acc[4] * iz2) * (1.f / 3.f) + b2[lane];
    float v1 = (acc[1] * iz0 + acc[3] * iz1 + acc[5] * iz2) * (1.f / 3.f) + b2[lane + 32];
    float* ph2 = g_h2 + (size_t)n * D64;
    ph2[lane] = v0;
    ph2[lane + 32] = v1;
    int b = batch[n];
    atomicAdd(&g_pool[b * D64 + lane], v0);
    atomicAdd(&g_pool[b * D64 + lane + 32], v1);
    if (lane == 0) atomicAdd(&g_cnt[b], 1.f);
}

__global__ void gat3_kernel(const float* __restrict__ att, const float* __restrict__ b3,
                            float* __restrict__ out) {
    __shared__ float sh[8][64];
    int tid = threadIdx.x;
    int lane = tid & 31, wib = tid >> 5;
    int n = blockIdx.x * 8 + wib;
    if (n >= NN) return;
    int c0 = lane, c1 = lane + 32;
    int h0 = c0 / D21;                     // 0 or 1
    int h1 = c1 / D21;                     // 1 or 2 (c1 < 63)
    bool v1ok = (c1 < HD63);
    float attr0 = att[c0], attr1 = v1ok ? att[c1] : 0.f;
    const float* pr = g_xr + (size_t)n * HD63;
    float xr0 = pr[c0], xr1 = v1ok ? pr[c1] : 0.f;
    float a0 = 0.f, a1 = 0.f;
    float m0 = -INFINITY, m1 = -INFINITY, m2 = -INFINITY;
    float z0 = 0.f, z1 = 0.f, z2 = 0.f;
    int e1 = g_rowptr[n + 1];
    for (int e = g_rowptr[n]; e < e1; e++) {
        int s = g_col[e];
        const float* px = g_xl + (size_t)s * HD63;
        float x0 = px[c0];
        float x1 = v1ok ? px[c1] : 0.f;
        float t0 = x0 + xr0; t0 = (t0 > 0.f) ? t0 : 0.2f * t0;
        float t1 = x1 + xr1; t1 = (t1 > 0.f) ? t1 : 0.2f * t1;
        float q0 = attr0 * t0, q1 = attr1 * t1;
        float p0 = (h0 == 0) ? q0 : 0.f;
        float p1 = ((h0 == 1) ? q0 : 0.f) + ((h1 == 1) ? q1 : 0.f);
        float p2 = (h1 == 2) ? q1 : 0.f;
        #pragma unroll
        for (int o = 16; o > 0; o >>= 1) {
            p0 += __shfl_xor_sync(0xffffffffu, p0, o);
            p1 += __shfl_xor_sync(0xffffffffu, p1, o);
            p2 += __shfl_xor_sync(0xffffffffu, p2, o);
        }
        float sc0, wt0, sc1, wt1, sc2, wt2;
        if (p0 > m0) { sc0 = __expf(m0 - p0); wt0 = 1.f; z0 = z0 * sc0 + 1.f; m0 = p0; }
        else         { sc0 = 1.f; wt0 = __expf(p0 - m0); z0 += wt0; }
        if (p1 > m1) { sc1 = __expf(m1 - p1); wt1 = 1.f; z1 = z1 * sc1 + 1.f; m1 = p1; }
        else         { sc1 = 1.f; wt1 = __expf(p1 - m1); z1 += wt1; }
        if (p2 > m2) { sc2 = __expf(m2 - p2); wt2 = 1.f; z2 = z2 * sc2 + 1.f; m2 = p2; }
        else         { sc2 = 1.f; wt2 = __expf(p2 - m2); z2 += wt2; }
        float sA0 = (h0 == 0) ? sc0 : sc1, wA0 = (h0 == 0) ? wt0 : wt1;
        float sA1 = (h1 == 1) ? sc1 : sc2, wA1 = (h1 == 1) ? wt1 : wt2;
        a0 = a0 * sA0 + x0 * wA0;
        a1 = a1 * sA1 + x1 * wA1;
    }
    float iz0 = 1.f / z0, iz1 = 1.f / z1, iz2 = 1.f / z2;
    sh[wib][c0] = a0 * ((h0 == 0) ? iz0 : iz1);
    if (v1ok) sh[wib][c1] = a1 * ((h1 == 1) ? iz1 : iz2);
    __syncwarp();
    if (lane < D21) {
        float o = (sh[wib][lane] + sh[wib][lane + D21] + sh[wib][lane + 2 * D21]) * (1.f / 3.f)
                  + b3[lane];
        out[NG * NCLS + (size_t)n * D21 + lane] = o;
    }
}

__global__ void classifier_kernel(const float* __restrict__ Wc, const float* __restrict__ bc,
                                  float* __restrict__ out) {
    int t = threadIdx.x;
    if (t >= NG * NCLS) return;
    int g = t / NCLS, j = t % NCLS;
    float cnt = fmaxf(g_cnt[g], 1.f);
    float s = bc[j];
    #pragma unroll
    for (int d = 0; d < D64; d++)
        s += (g_pool[g * D64 + d] / cnt) * Wc[d * NCLS + j];
    out[t] = s;
}

// ---------------- launch ----------------
extern "C" void kernel_launch(void* const* d_in, const int* in_sizes, int n_in,
                              void* d_out, int out_size) {
    const float* x     = (const float*)d_in[0];
    const int*   ei    = (const int*)d_in[1];
    const int*   batch = (const int*)d_in[2];
    const float* Wl1   = (const float*)d_in[3];
    const float* Wr1   = (const float*)d_in[4];
    const float* att1  = (const float*)d_in[5];
    const float* b1    = (const float*)d_in[6];
    const float* gamma = (const float*)d_in[7];
    const float* beta  = (const float*)d_in[8];
    const float* Wl2   = (const float*)d_in[9];
    const float* Wr2   = (const float*)d_in[10];
    const float* att2  = (const float*)d_in[11];
    const float* b2    = (const float*)d_in[12];
    const float* Wl3   = (const float*)d_in[13];
    const float* Wr3   = (const float*)d_in[14];
    const float* att3  = (const float*)d_in[15];
    const float* b3    = (const float*)d_in[16];
    const float* Wc    = (const float*)d_in[17];
    const float* bc    = (const float*)d_in[18];
    float* out = (float*)d_out;

    const int* src  = ei;
    const int* dstp = ei + NE;

    float *pxl, *pxr, *ph, *ph2;
    cudaGetSymbolAddress((void**)&pxl, g_xl);
    cudaGetSymbolAddress((void**)&pxr, g_xr);
    cudaGetSymbolAddress((void**)&ph,  g_h);
    cudaGetSymbolAddress((void**)&ph2, g_h2);

    reset_small_kernel<<<1, 512>>>();

    // CSR build (reused by all three layers)
    init_counts_kernel<<<(NN + 255) / 256, 256>>>();
    hist_kernel<<<(NE + 255) / 256, 256>>>(dstp);
    scan_kernel<<<1, 1024>>>();
    csr_fill_kernel<<<(ETOT + 255) / 256, 256>>>(src, dstp);

    const int gat_grid = (NN + 7) / 8;   // 8 warps (nodes) per 256-thread block
    dim3 gy192(3, (NN + BM - 1) / BM);   // N=192 -> 3 tiles of 64
    dim3 gy63(1, (NN + BM - 1) / BM);    // N=63  -> 1 tile

    // ---- layer 1: x(128) -> 3x64 concat ----
    gemm_kernel<<<gy192, 256>>>(x, Wl1, pxl, NN, HD192, 128, 0);
    gemm_kernel<<<gy192, 256>>>(x, Wr1, pxr, NN, HD192, 128, 0);
    gat1_kernel<<<gat_grid, 256>>>(att1, b1);
    bn_prep_kernel<<<1, 256>>>(gamma, beta);

    // ---- layer 2: BN(h)(192) -> 64 (head mean), + pooling ----
    gemm_kernel<<<gy192, 256>>>(ph, Wl2, pxl, NN, HD192, HD192, 2);
    gemm_kernel<<<gy192, 256>>>(ph, Wr2, pxr, NN, HD192, HD192, 2);
    gat2_kernel<<<gat_grid, 256>>>(att2, b2, batch);
    classifier_kernel<<<1, 128>>>(Wc, bc, out);

    // ---- layer 3: relu(h2)(64) -> 21 (head mean) ----
    gemm_kernel<<<gy63, 256>>>(ph2, Wl3, pxl, NN, HD63, D64, 1);
    gemm_kernel<<<gy63, 256>>>(ph2, Wr3, pxr, NN, HD63, D64, 1);
    gat3_kernel<<<gat_grid, 256>>>(att3, b3, out);
}

// round 6
// speedup vs baseline: 3.0655x; 1.1525x over previous
#include <cuda_runtime.h>
#include <math.h>
#include <stdint.h>

#define NN 100000
#define NE 1600000
#define ETOT (NE + NN)
#define HD192 192
#define D64 64
#define HD63 63
#define D21 21
#define NG 8
#define NCLS 10
#define EPSBN 1e-5f
#define SBLK 98          // scan blocks: 98 * 1024 >= NN

// ---------------- scratch (device globals; no allocs allowed) ----------------
__device__ float g_xl[(size_t)NN * HD192];
__device__ float g_xr[(size_t)NN * HD192];
__device__ float g_h[(size_t)NN * HD192];
__device__ float g_h2[(size_t)NN * D64];
__device__ int   g_counts[NN];
__device__ int   g_rowptr[NN + 1];
__device__ int   g_cursor[NN];
__device__ int   g_col[ETOT];
__device__ int   g_bsum[SBLK];
__device__ int   g_boff[SBLK];
__device__ float g_bnsum[HD192];
__device__ float g_bnsq[HD192];
__device__ float g_bnscale[HD192];
__device__ float g_bnshift[HD192];
__device__ float g_pool[NG * D64];
__device__ float g_cnt[NG];

// ---------------- small resets ----------------
__global__ void reset_small_kernel() {
    int t = threadIdx.x;
    if (t < HD192) { g_bnsum[t] = 0.f; g_bnsq[t] = 0.f; }
    if (t < NG * D64) g_pool[t] = 0.f;
    if (t < NG) g_cnt[t] = 0.f;
}

// ---------------- CSR build (dst-sorted, rebuilt each launch) ----------------
__global__ void init_counts_kernel() {
    int i = blockIdx.x * blockDim.x + threadIdx.x;
    if (i < NN) g_counts[i] = 1;   // self loop
}

__global__ void hist_kernel(const int* __restrict__ dst) {
    int e = blockIdx.x * blockDim.x + threadIdx.x;
    if (e < NE) atomicAdd(&g_counts[dst[e]], 1);
}

// hierarchical scan: per-block partial sums
__global__ void scan1_kernel() {
    __shared__ int ss[256];
    int t = threadIdx.x, b = blockIdx.x;
    int base = b * 1024 + t * 4;
    int s = 0;
    #pragma unroll
    for (int q = 0; q < 4; q++) { int i = base + q; if (i < NN) s += g_counts[i]; }
    ss[t] = s;
    __syncthreads();
    for (int off = 1; off < 256; off <<= 1) {
        int v = (t >= off) ? ss[t - off] : 0;
        __syncthreads();
        ss[t] += v;
        __syncthreads();
    }
    if (t == 255) g_bsum[b] = ss[255];
}

__global__ void scan2_kernel() {
    __shared__ int ss[128];
    int t = threadIdx.x;
    ss[t] = (t < SBLK) ? g_bsum[t] : 0;
    __syncthreads();
    for (int off = 1; off < 128; off <<= 1) {
        int v = (t >= off) ? ss[t - off] : 0;
        __syncthreads();
        ss[t] += v;
        __syncthreads();
    }
    if (t < SBLK) g_boff[t] = t ? ss[t - 1] : 0;
    if (t == 127) g_rowptr[NN] = ss[127];
}

__global__ void scan3_kernel() {
    __shared__ int ss[256];
    int t = threadIdx.x, b = blockIdx.x;
    int base = b * 1024 + t * 4;
    int cnt[4]; int s = 0;
    #pragma unroll
    for (int q = 0; q < 4; q++) {
        cnt[q] = (base + q < NN) ? g_counts[base + q] : 0;
        s += cnt[q];
    }
    ss[t] = s;
    __syncthreads();
    for (int off = 1; off < 256; off <<= 1) {
        int v = (t >= off) ? ss[t - off] : 0;
        __syncthreads();
        ss[t] += v;
        __syncthreads();
    }
    int pre = g_boff[b] + (t ? ss[t - 1] : 0);
    #pragma unroll
    for (int q = 0; q < 4; q++) {
        int i = base + q;
        if (i < NN) { g_rowptr[i] = pre; g_cursor[i] = pre; pre += cnt[q]; }
    }
}

__global__ void csr_fill_kernel(const int* __restrict__ src, const int* __restrict__ dst) {
    int e = blockIdx.x * blockDim.x + threadIdx.x;
    if (e >= ETOT) return;
    int s, d;
    if (e < NE) { s = src[e]; d = dst[e]; } else { s = d = e - NE; }
    int pos = atomicAdd(&g_cursor[d], 1);
    g_col[pos] = s;
}

// ---------------- TF32 tensor-core GEMM ----------------
// C[M,N] = f(A)[M,K] @ B[K,N]; mode 0=id, 1=relu(A), 2=BN(A)
// block 256 thr = 8 warps (4 along M x 2 along N), block tile 128x64, warp tile 32x32
// blockIdx.z selects (Bl,Cl) vs (Br,Cr).
#define SAS 136    // sA m-stride (== 8 mod 32 -> conflict-free frag loads)

__device__ __forceinline__ uint32_t f2tf32(float f) {
    uint32_t u;
    asm("cvt.rna.tf32.f32 %0, %1;" : "=r"(u) : "f"(f));
    return u;
}

__global__ void gemm_tf32_kernel(const float* __restrict__ A,
                                 const float* __restrict__ Bl, const float* __restrict__ Br,
                                 float* __restrict__ Cl, float* __restrict__ Cr,
                                 int M, int N, int K, int mode) {
    extern __shared__ uint32_t smem[];
    const int K4 = K + 4;                 // == 4 mod 32 -> conflict-free B frag loads
    uint32_t* sBT = smem;                 // [64][K4]  (n-major, transposed)
    uint32_t* sA  = smem + 64 * K4;       // [32][SAS] (k-major)

    int tid = threadIdx.x;
    const float* Bg = blockIdx.z ? Br : Bl;
    float* Cg = blockIdx.z ? Cr : Cl;
    int col0 = blockIdx.x * 64;
    int row0 = blockIdx.y * 128;

    // stage full B slab (K x 64), transposed + tf32
    for (int i = tid; i < K * 16; i += 256) {
        int k = i >> 4, n4 = (i & 15) * 4;
        #pragma unroll
        for (int q = 0; q < 4; q++) {
            int n = n4 + q;
            float v = (col0 + n < N) ? Bg[(size_t)k * N + col0 + n] : 0.f;
            sBT[n * K4 + k] = f2tf32(v);
        }
    }

    int lane = tid & 31, w = tid >> 5;
    int mw = (w & 3) * 32, nw = (w >> 2) * 32;
    int g = lane >> 2, c = lane & 3;

    float acc[2][4][4] = {};

    for (int k0 = 0; k0 < K; k0 += 32) {
        // stage A chunk 128 x 32 (tf32, k-major)
        #pragma unroll
        for (int l = 0; l < 4; l++) {
            int i = tid + l * 256;
            int r = i >> 3, c4 = (i & 7) * 4;
            int gr = row0 + r;
            float4 v = make_float4(0.f, 0.f, 0.f, 0.f);
            if (gr < M) v = *(const float4*)&A[(size_t)gr * K + k0 + c4];
            float vv[4] = {v.x, v.y, v.z, v.w};
            #pragma unroll
            for (int q = 0; q < 4; q++) {
                float f = vv[q];
                int kc = k0 + c4 + q;
                if (mode == 1) f = fmaxf(f, 0.f);
                else if (mode == 2) f = f * g_bnscale[kc] + g_bnshift[kc];
                sA[(c4 + q) * SAS + r] = f2tf32(f);
            }
        }
        __syncthreads();

        #pragma unroll
        for (int kk = 0; kk < 32; kk += 8) {
            uint32_t af[2][4], bf[4][2];
            #pragma unroll
            for (int mt = 0; mt < 2; mt++) {
                int mb = mw + mt * 16 + g;
                af[mt][0] = sA[(kk + c) * SAS + mb];
                af[mt][1] = sA[(kk + c) * SAS + mb + 8];
                af[mt][2] = sA[(kk + c + 4) * SAS + mb];
                af[mt][3] = sA[(kk + c + 4) * SAS + mb + 8];
            }
            #pragma unroll
            for (int nt = 0; nt < 4; nt++) {
                int nb = nw + nt * 8 + g;
                bf[nt][0] = sBT[nb * K4 + k0 + kk + c];
                bf[nt][1] = sBT[nb * K4 + k0 + kk + c + 4];
            }
            #pragma unroll
            for (int mt = 0; mt < 2; mt++)
                #pragma unroll
                for (int nt = 0; nt < 4; nt++) {
                    float* cc = acc[mt][nt];
                    asm volatile(
                        "mma.sync.aligned.m16n8k8.row.col.f32.tf32.tf32.f32 "
                        "{%0,%1,%2,%3}, {%4,%5,%6,%7}, {%8,%9}, {%0,%1,%2,%3};"
                        : "+f"(cc[0]), "+f"(cc[1]), "+f"(cc[2]), "+f"(cc[3])
                        : "r"(af[mt][0]), "r"(af[mt][1]), "r"(af[mt][2]), "r"(af[mt][3]),
                          "r"(bf[nt][0]), "r"(bf[nt][1]));
                }
        }
        __syncthreads();
    }

    // epilogue
    #pragma unroll
    for (int mt = 0; mt < 2; mt++) {
        #pragma unroll
        for (int nt = 0; nt < 4; nt++) {
            int row = row0 + mw + mt * 16 + g;
            int col = col0 + nw + nt * 8 + 2 * c;
            float* cc = acc[mt][nt];
            if (row < M) {
                if (col < N)     Cg[(size_t)row * N + col]     = cc[0];
                if (col + 1 < N) Cg[(size_t)row * N + col + 1] = cc[1];
            }
            if (row + 8 < M) {
                if (col < N)     Cg[(size_t)(row + 8) * N + col]     = cc[2];
                if (col + 1 < N) Cg[(size_t)(row + 8) * N + col + 1] = cc[3];
            }
        }
    }
}

// ---------------- fused GAT layers (warp per node, online softmax) ----------------
#define ONLINE_UPDATE(P, M, Z, A0, A1, X0, X1)                          \
    if (P > M) {                                                         \
        float sc_ = __expf(M - P); Z = Z * sc_ + 1.f;                    \
        A0 = A0 * sc_ + X0; A1 = A1 * sc_ + X1; M = P;                   \
    } else {                                                             \
        float w_ = __expf(P - M); Z += w_;                               \
        A0 += X0 * w_; A1 += X1 * w_;                                    \
    }

__global__ void gat1_kernel(const float* __restrict__ att, const float* __restrict__ b1) {
    __shared__ float sbn[HD192], sbq[HD192];
    int tid = threadIdx.x;
    if (tid < HD192) { sbn[tid] = 0.f; sbq[tid] = 0.f; }
    __syncthreads();
    int lane = tid & 31, wib = tid >> 5;
    int n = blockIdx.x * 8 + wib;
    if (n < NN) {
        float attr[6], xrr[6], acc[6], xv[6];
        const float* pr = g_xr + (size_t)n * HD192;
        #pragma unroll
        for (int i = 0; i < 6; i++) {
            int c = lane + 32 * i;
            attr[i] = att[c]; xrr[i] = pr[c]; acc[i] = 0.f;
        }
        float m0 = -INFINITY, m1 = -INFINITY, m2 = -INFINITY;
        float z0 = 0.f, z1 = 0.f, z2 = 0.f;
        int e1 = g_rowptr[n + 1];
        for (int e = g_rowptr[n]; e < e1; e++) {
            int s = g_col[e];
            const float* px = g_xl + (size_t)s * HD192;
            float p0 = 0.f, p1 = 0.f, p2 = 0.f;
            #pragma unroll
            for (int i = 0; i < 6; i++) {
                int c = lane + 32 * i;
                float xvv = px[c]; xv[i] = xvv;
                float v = xvv + xrr[i];
                v = (v > 0.f) ? v : 0.2f * v;
                float pv = attr[i] * v;
                if (i < 2) p0 += pv; else if (i < 4) p1 += pv; else p2 += pv;
            }
            #pragma unroll
            for (int o = 16; o > 0; o >>= 1) {
                p0 += __shfl_xor_sync(0xffffffffu, p0, o);
                p1 += __shfl_xor_sync(0xffffffffu, p1, o);
                p2 += __shfl_xor_sync(0xffffffffu, p2, o);
            }
            ONLINE_UPDATE(p0, m0, z0, acc[0], acc[1], xv[0], xv[1])
            ONLINE_UPDATE(p1, m1, z1, acc[2], acc[3], xv[2], xv[3])
            ONLINE_UPDATE(p2, m2, z2, acc[4], acc[5], xv[4], xv[5])
        }
        float iz[3] = {1.f / z0, 1.f / z1, 1.f / z2};
        float* ph = g_h + (size_t)n * HD192;
        #pragma unroll
        for (int i = 0; i < 6; i++) {
            int c = lane + 32 * i;
            float o = acc[i] * iz[i >> 1] + b1[c];
            o = fmaxf(o, 0.f);
            ph[c] = o;
            atomicAdd(&sbn[c], o);
            atomicAdd(&sbq[c], o * o);
        }
    }
    __syncthreads();
    if (tid < HD192) {
        atomicAdd(&g_bnsum[tid], sbn[tid]);
        atomicAdd(&g_bnsq[tid], sbq[tid]);
    }
}

__global__ void bn_prep_kernel(const float* __restrict__ gamma, const float* __restrict__ beta) {
    int c = threadIdx.x;
    if (c < HD192) {
        float mu = g_bnsum[c] * (1.f / NN);
        float var = g_bnsq[c] * (1.f / NN) - mu * mu;
        float s = gamma[c] * rsqrtf(var + EPSBN);
        g_bnscale[c] = s;
        g_bnshift[c] = beta[c] - mu * s;
    }
}

__global__ void gat2_kernel(const float* __restrict__ att, const float* __restrict__ b2,
                            const int* __restrict__ batch) {
    int tid = threadIdx.x;
    int lane = tid & 31, wib = tid >> 5;
    int n = blockIdx.x * 8 + wib;
    if (n >= NN) return;
    float attr[6], xrr[6], acc[6], xv[6];
    const float* pr = g_xr + (size_t)n * HD192;
    #pragma unroll
    for (int i = 0; i < 6; i++) {
        int c = lane + 32 * i;
        attr[i] = att[c]; xrr[i] = pr[c]; acc[i] = 0.f;
    }
    float m0 = -INFINITY, m1 = -INFINITY, m2 = -INFINITY;
    float z0 = 0.f, z1 = 0.f, z2 = 0.f;
    int e1 = g_rowptr[n + 1];
    for (int e = g_rowptr[n]; e < e1; e++) {
        int s = g_col[e];
        const float* px = g_xl + (size_t)s * HD192;
        float p0 = 0.f, p1 = 0.f, p2 = 0.f;
        #pragma unroll
        for (int i = 0; i < 6; i++) {
            int c = lane + 32 * i;
            float xvv = px[c]; xv[i] = xvv;
            float v = xvv + xrr[i];
            v = (v > 0.f) ? v : 0.2f * v;
            float pv = attr[i] * v;
            if (i < 2) p0 += pv; else if (i < 4) p1 += pv; else p2 += pv;
        }
        #pragma unroll
        for (int o = 16; o > 0; o >>= 1) {
            p0 += __shfl_xor_sync(0xffffffffu, p0, o);
            p1 += __shfl_xor_sync(0xffffffffu, p1, o);
            p2 += __shfl_xor_sync(0xffffffffu, p2, o);
        }
        ONLINE_UPDATE(p0, m0, z0, acc[0], acc[1], xv[0], xv[1])
        ONLINE_UPDATE(p1, m1, z1, acc[2], acc[3], xv[2], xv[3])
        ONLINE_UPDATE(p2, m2, z2, acc[4], acc[5], xv[4], xv[5])
    }
    float iz0 = 1.f / z0, iz1 = 1.f / z1, iz2 = 1.f / z2;
    float v0 = (acc[0] * iz0 + acc[2] * iz1 + acc[4] * iz2) * (1.f / 3.f) + b2[lane];
    float v1 = (acc[1] * iz0 + acc[3] * iz1 + acc[5] * iz2) * (1.f / 3.f) + b2[lane + 32];
    float* ph2 = g_h2 + (size_t)n * D64;
    ph2[lane] = v0;
    ph2[lane + 32] = v1;
    int b = batch[n];
    atomicAdd(&g_pool[b * D64 + lane], v0);
    atomicAdd(&g_pool[b * D64 + lane + 32], v1);
    if (lane == 0) atomicAdd(&g_cnt[b], 1.f);
}

__global__ void gat3_kernel(const float* __restrict__ att, const float* __restrict__ b3,
                            float* __restrict__ out) {
    __shared__ float sh[8][64];
    int tid = threadIdx.x;
    int lane = tid & 31, wib = tid >> 5;
    int n = blockIdx.x * 8 + wib;
    if (n >= NN) return;
    int c0 = lane, c1 = lane + 32;
    int h0 = c0 / D21;
    int h1 = c1 / D21;
    bool v1ok = (c1 < HD63);
    float attr0 = att[c0], attr1 = v1ok ? att[c1] : 0.f;
    const float* pr = g_xr + (size_t)n * HD63;
    float xr0 = pr[c0], xr1 = v1ok ? pr[c1] : 0.f;
    float a0 = 0.f, a1 = 0.f;
    float m0 = -INFINITY, m1 = -INFINITY, m2 = -INFINITY;
    float z0 = 0.f, z1 = 0.f, z2 = 0.f;
    int e1 = g_rowptr[n + 1];
    for (int e = g_rowptr[n]; e < e1; e++) {
        int s = g_col[e];
        const float* px = g_xl + (size_t)s * HD63;
        float x0 = px[c0];
        float x1 = v1ok ? px[c1] : 0.f;
        float t0 = x0 + xr0; t0 = (t0 > 0.f) ? t0 : 0.2f * t0;
        float t1 = x1 + xr1; t1 = (t1 > 0.f) ? t1 : 0.2f * t1;
        float q0 = attr0 * t0, q1 = attr1 * t1;
        float p0 = (h0 == 0) ? q0 : 0.f;
        float p1 = ((h0 == 1) ? q0 : 0.f) + ((h1 == 1) ? q1 : 0.f);
        float p2 = (h1 == 2) ? q1 : 0.f;
        #pragma unroll
        for (int o = 16; o > 0; o >>= 1) {
            p0 += __shfl_xor_sync(0xffffffffu, p0, o);
            p1 += __shfl_xor_sync(0xffffffffu, p1, o);
            p2 += __shfl_xor_sync(0xffffffffu, p2, o);
        }
        float sc0, wt0, sc1, wt1, sc2, wt2;
        if (p0 > m0) { sc0 = __expf(m0 - p0); wt0 = 1.f; z0 = z0 * sc0 + 1.f; m0 = p0; }
        else         { sc0 = 1.f; wt0 = __expf(p0 - m0); z0 += wt0; }
        if (p1 > m1) { sc1 = __expf(m1 - p1); wt1 = 1.f; z1 = z1 * sc1 + 1.f; m1 = p1; }
        else         { sc1 = 1.f; wt1 = __expf(p1 - m1); z1 += wt1; }
        if (p2 > m2) { sc2 = __expf(m2 - p2); wt2 = 1.f; z2 = z2 * sc2 + 1.f; m2 = p2; }
        else         { sc2 = 1.f; wt2 = __expf(p2 - m2); z2 += wt2; }
        float sA0 = (h0 == 0) ? sc0 : sc1, wA0 = (h0 == 0) ? wt0 : wt1;
        float sA1 = (h1 == 1) ? sc1 : sc2, wA1 = (h1 == 1) ? wt1 : wt2;
        a0 = a0 * sA0 + x0 * wA0;
        a1 = a1 * sA1 + x1 * wA1;
    }
    float iz0 = 1.f / z0, iz1 = 1.f / z1, iz2 = 1.f / z2;
    sh[wib][c0] = a0 * ((h0 == 0) ? iz0 : iz1);
    if (v1ok) sh[wib][c1] = a1 * ((h1 == 1) ? iz1 : iz2);
    __syncwarp();
    if (lane < D21) {
        float o = (sh[wib][lane] + sh[wib][lane + D21] + sh[wib][lane + 2 * D21]) * (1.f / 3.f)
                  + b3[lane];
        out[NG * NCLS + (size_t)n * D21 + lane] = o;
    }
}

__global__ void classifier_kernel(const float* __restrict__ Wc, const float* __restrict__ bc,
                                  float* __restrict__ out) {
    int t = threadIdx.x;
    if (t >= NG * NCLS) return;
    int g = t / NCLS, j = t % NCLS;
    float cnt = fmaxf(g_cnt[g], 1.f);
    float s = bc[j];
    #pragma unroll
    for (int d = 0; d < D64; d++)
        s += (g_pool[g * D64 + d] / cnt) * Wc[d * NCLS + j];
    out[t] = s;
}

// ---------------- launch ----------------
extern "C" void kernel_launch(void* const* d_in, const int* in_sizes, int n_in,
                              void* d_out, int out_size) {
    const float* x     = (const float*)d_in[0];
    const int*   ei    = (const int*)d_in[1];
    const int*   batch = (const int*)d_in[2];
    const float* Wl1   = (const float*)d_in[3];
    const float* Wr1   = (const float*)d_in[4];
    const float* att1  = (const float*)d_in[5];
    const float* b1    = (const float*)d_in[6];
    const float* gamma = (const float*)d_in[7];
    const float* beta  = (const float*)d_in[8];
    const float* Wl2   = (const float*)d_in[9];
    const float* Wr2   = (const float*)d_in[10];
    const float* att2  = (const float*)d_in[11];
    const float* b2    = (const float*)d_in[12];
    const float* Wl3   = (const float*)d_in[13];
    const float* Wr3   = (const float*)d_in[14];
    const float* att3  = (const float*)d_in[15];
    const float* b3    = (const float*)d_in[16];
    const float* Wc    = (const float*)d_in[17];
    const float* bc    = (const float*)d_in[18];
    float* out = (float*)d_out;

    const int* src  = ei;
    const int* dstp = ei + NE;

    float *pxl, *pxr, *ph, *ph2;
    cudaGetSymbolAddress((void**)&pxl, g_xl);
    cudaGetSymbolAddress((void**)&pxr, g_xr);
    cudaGetSymbolAddress((void**)&ph,  g_h);
    cudaGetSymbolAddress((void**)&ph2, g_h2);

    // dynamic smem sizes: (64*(K+4) + 32*SAS) * 4 bytes
    auto smem_for = [](int K) { return (size_t)(64 * (K + 4) + 32 * SAS) * 4; };
    static bool attr_set = false;
    if (!attr_set) {
        cudaFuncSetAttribute(gemm_tf32_kernel,
                             cudaFuncAttributeMaxDynamicSharedMemorySize,
                             (int)smem_for(HD192));
        attr_set = true;
    }

    reset_small_kernel<<<1, 512>>>();

    // CSR build (reused by all three layers)
    init_counts_kernel<<<(NN + 255) / 256, 256>>>();
    hist_kernel<<<(NE + 255) / 256, 256>>>(dstp);
    scan1_kernel<<<SBLK, 256>>>();
    scan2_kernel<<<1, 128>>>();
    scan3_kernel<<<SBLK, 256>>>();
    csr_fill_kernel<<<(ETOT + 255) / 256, 256>>>(src, dstp);

    const int gat_grid = (NN + 7) / 8;
    const int my = (NN + 127) / 128;

    // ---- layer 1: x(128) -> 3x64 concat ----
    {
        dim3 g(3, my, 2);
        gemm_tf32_kernel<<<g, 256, smem_for(128)>>>(x, Wl1, Wr1, pxl, pxr, NN, HD192, 128, 0);
    }
    gat1_kernel<<<gat_grid, 256>>>(att1, b1);
    bn_prep_kernel<<<1, 256>>>(gamma, beta);

    // ---- layer 2: BN(h)(192) -> 64 (head mean), + pooling ----
    {
        dim3 g(3, my, 2);
        gemm_tf32_kernel<<<g, 256, smem_for(HD192)>>>(ph, Wl2, Wr2, pxl, pxr, NN, HD192, HD192, 2);
    }
    gat2_kernel<<<gat_grid, 256>>>(att2, b2, batch);
    classifier_kernel<<<1, 128>>>(Wc, bc, out);

    // ---- layer 3: relu(h2)(64) -> 21 (head mean) ----
    {
        dim3 g(1, my, 2);
        gemm_tf32_kernel<<<g, 256, smem_for(D64)>>>(ph2, Wl3, Wr3, pxl, pxr, NN, HD63, D64, 1);
    }
    gat3_kernel<<<gat_grid, 256>>>(att3, b3, out);
}